// round 1
// baseline (speedup 1.0000x reference)
#include <cuda_runtime.h>

#define BNUM 2
#define SLEN 2048
#define DDIM 1024
#define HNUM 16
#define DKQ  64

// Scratch for projected Q/K/V in [B, H, S, DK] layout (16 MB each).
__device__ float g_q[BNUM*HNUM*SLEN*DKQ];
__device__ float g_k[BNUM*HNUM*SLEN*DKQ];
__device__ float g_v[BNUM*HNUM*SLEN*DKQ];

// C[M=4096, N=1024] = A[4096,1024] @ W[1024,1024] + bias, stored to out in
// [B, H, S, DK] layout. Tile: BM=64, BN=64, BK=16. 128 threads, 4x8 per thread.
__global__ __launch_bounds__(128) void proj_kernel(
    const float* __restrict__ A, const float* __restrict__ W,
    const float* __restrict__ bias, float* __restrict__ out)
{
    __shared__ float As[64][17];   // [row][k]
    __shared__ float Ws[16][68];   // [k][col], 272B rows (16B aligned)

    const int tid = threadIdx.x;
    const int rg  = tid >> 3;      // 0..15 -> rows rg*4..rg*4+3
    const int cg  = tid & 7;       // 0..7  -> cols cg*8..cg*8+7
    const int row0 = blockIdx.y << 6;
    const int col0 = blockIdx.x << 6;

    float acc[4][8];
#pragma unroll
    for (int i = 0; i < 4; i++)
#pragma unroll
        for (int j = 0; j < 8; j++) acc[i][j] = 0.f;

    for (int kt = 0; kt < DDIM; kt += 16) {
        // Load A tile 64x16 and W tile 16x64 (256 float4 each, 2 per thread).
#pragma unroll
        for (int it = 0; it < 2; it++) {
            int f = tid + it * 128;
            int r = f >> 2, c = (f & 3) << 2;
            float4 va = *(const float4*)(A + (size_t)(row0 + r) * DDIM + kt + c);
            As[r][c]   = va.x; As[r][c+1] = va.y;
            As[r][c+2] = va.z; As[r][c+3] = va.w;
            int rw = f >> 4, cw = (f & 15) << 2;
            *(float4*)&Ws[rw][cw] =
                *(const float4*)(W + (size_t)(kt + rw) * DDIM + col0 + cw);
        }
        __syncthreads();

#pragma unroll
        for (int k = 0; k < 16; k++) {
            float a[4], b[8];
#pragma unroll
            for (int i = 0; i < 4; i++) a[i] = As[rg*4 + i][k];
#pragma unroll
            for (int j = 0; j < 8; j++) b[j] = Ws[k][cg*8 + j];
#pragma unroll
            for (int i = 0; i < 4; i++)
#pragma unroll
                for (int j = 0; j < 8; j++)
                    acc[i][j] = fmaf(a[i], b[j], acc[i][j]);
        }
        __syncthreads();
    }

    // col0 is a multiple of 64, so the whole 64-col block belongs to one head.
    const int h = col0 >> 6;
#pragma unroll
    for (int i = 0; i < 4; i++) {
        int m = row0 + rg*4 + i;
        int b = m >> 11;           // /S
        int s = m & (SLEN - 1);
        float* orow = out + ((size_t)(b*HNUM + h) * SLEN + s) * DKQ + cg*8;
#pragma unroll
        for (int j = 0; j < 8; j++)
            orow[j] = acc[i][j] + bias[col0 + cg*8 + j];
    }
}

// Flash attention, causal. One block = (bh, 64-query tile). 128 threads,
// 4x8 per-thread microtiles for both the QK^T and PV GEMM phases.
// Smem layouts chosen for conflict-free inner-loop LDS:
//   Qst [d][qrow] stride 65, Kst [d][key] stride 65,
//   Pst [key][qrow] stride 65, Vs [key][d] stride 68 (float4 loads).
__global__ __launch_bounds__(128) void attn_kernel(
    const float* __restrict__ Q, const float* __restrict__ K,
    const float* __restrict__ V, float* __restrict__ out)
{
    extern __shared__ float smem[];
    float* Qst = smem;               // 64*65
    float* Kst = smem + 64*65;       // 64*65
    float* Pst = smem + 2*64*65;     // 64*65
    float* Vs  = smem + 3*64*65;     // 64*68

    const int tid = threadIdx.x;
    const int rg  = tid >> 3;        // query-row group (4 rows)
    const int cg  = tid & 7;         // col group (8 cols)
    const int bh  = blockIdx.x;      // b*H + h
    const int qt  = blockIdx.y;      // query tile

    const float* Qb = Q + ((size_t)bh * SLEN + (size_t)qt * 64) * DKQ;

    // Load Q tile transposed (d-major).
#pragma unroll
    for (int it = 0; it < 8; it++) {
        int f = tid + it * 128;
        int r = f >> 4, c = (f & 15) << 2;
        float4 v4 = *(const float4*)(Qb + r * DKQ + c);
        Qst[(c+0)*65 + r] = v4.x;
        Qst[(c+1)*65 + r] = v4.y;
        Qst[(c+2)*65 + r] = v4.z;
        Qst[(c+3)*65 + r] = v4.w;
    }

    float m[4], l[4], acc[4][8];
#pragma unroll
    for (int i = 0; i < 4; i++) {
        m[i] = -1e30f; l[i] = 0.f;
#pragma unroll
        for (int j = 0; j < 8; j++) acc[i][j] = 0.f;
    }

    const float scale = 0.125f;      // 1/sqrt(64)
    const int q0 = qt*64 + rg*4;

    for (int kt = 0; kt <= qt; kt++) {
        __syncthreads();             // prior-iter Pst/Vs readers done (also covers Qst first use)
        const float* Kb = K + ((size_t)bh * SLEN + (size_t)kt * 64) * DKQ;
        const float* Vb = V + ((size_t)bh * SLEN + (size_t)kt * 64) * DKQ;
#pragma unroll
        for (int it = 0; it < 8; it++) {
            int f = tid + it * 128;
            int r = f >> 4, c = (f & 15) << 2;
            float4 k4 = *(const float4*)(Kb + r * DKQ + c);
            Kst[(c+0)*65 + r] = k4.x;
            Kst[(c+1)*65 + r] = k4.y;
            Kst[(c+2)*65 + r] = k4.z;
            Kst[(c+3)*65 + r] = k4.w;
            *(float4*)&Vs[r*68 + c] = *(const float4*)(Vb + r * DKQ + c);
        }
        __syncthreads();

        // Scores: sc[i][j] = sum_d Q[q0+i][d] * K[k0+j][d]
        float sc[4][8];
#pragma unroll
        for (int i = 0; i < 4; i++)
#pragma unroll
            for (int j = 0; j < 8; j++) sc[i][j] = 0.f;

#pragma unroll 8
        for (int d = 0; d < 64; d++) {
            float a[4], b[8];
#pragma unroll
            for (int i = 0; i < 4; i++) a[i] = Qst[d*65 + rg*4 + i];
#pragma unroll
            for (int j = 0; j < 8; j++) b[j] = Kst[d*65 + cg*8 + j];
#pragma unroll
            for (int i = 0; i < 4; i++)
#pragma unroll
                for (int j = 0; j < 8; j++)
                    sc[i][j] = fmaf(a[i], b[j], sc[i][j]);
        }

        const int k0 = kt*64 + cg*8;
        if (kt == qt) {
#pragma unroll
            for (int i = 0; i < 4; i++)
#pragma unroll
                for (int j = 0; j < 8; j++)
                    sc[i][j] = (k0 + j > q0 + i) ? -1e30f : sc[i][j] * scale;
        } else {
#pragma unroll
            for (int i = 0; i < 4; i++)
#pragma unroll
                for (int j = 0; j < 8; j++) sc[i][j] *= scale;
        }

        // Online softmax per row; rows split across 8 contiguous lanes.
#pragma unroll
        for (int i = 0; i < 4; i++) {
            float rmax = sc[i][0];
#pragma unroll
            for (int j = 1; j < 8; j++) rmax = fmaxf(rmax, sc[i][j]);
#pragma unroll
            for (int off = 1; off < 8; off <<= 1)
                rmax = fmaxf(rmax, __shfl_xor_sync(0xffffffffu, rmax, off));
            float mn   = fmaxf(m[i], rmax);
            float corr = __expf(m[i] - mn);
            float rsum = 0.f;
#pragma unroll
            for (int j = 0; j < 8; j++) {
                sc[i][j] = __expf(sc[i][j] - mn);
                rsum += sc[i][j];
            }
#pragma unroll
            for (int off = 1; off < 8; off <<= 1)
                rsum += __shfl_xor_sync(0xffffffffu, rsum, off);
            l[i] = l[i] * corr + rsum;
            m[i] = mn;
#pragma unroll
            for (int j = 0; j < 8; j++) {
                acc[i][j] *= corr;
                Pst[(cg*8 + j)*65 + rg*4 + i] = sc[i][j];
            }
        }
        __syncthreads();

        // acc += P @ V
#pragma unroll 8
        for (int kk = 0; kk < 64; kk++) {
            float a[4], b[8];
#pragma unroll
            for (int i = 0; i < 4; i++) a[i] = Pst[kk*65 + rg*4 + i];
#pragma unroll
            for (int j = 0; j < 8; j++) b[j] = Vs[kk*68 + cg*8 + j];
#pragma unroll
            for (int i = 0; i < 4; i++)
#pragma unroll
                for (int j = 0; j < 8; j++)
                    acc[i][j] = fmaf(a[i], b[j], acc[i][j]);
        }
    }

    // Epilogue: out is [B, S, D] with D = H*DK.
    const int b = bh >> 4, h = bh & 15;
#pragma unroll
    for (int i = 0; i < 4; i++) {
        int srow = qt*64 + rg*4 + i;
        float inv = 1.f / l[i];
        float* orow = out + ((size_t)b * SLEN + srow) * DDIM + h * DKQ + cg*8;
#pragma unroll
        for (int j = 0; j < 8; j++)
            orow[j] = acc[i][j] * inv;
    }
}

extern "C" void kernel_launch(void* const* d_in, const int* in_sizes, int n_in,
                              void* d_out, int out_size) {
    const float* q  = (const float*)d_in[0];
    const float* k  = (const float*)d_in[1];
    const float* v  = (const float*)d_in[2];
    const float* Wq = (const float*)d_in[3];
    const float* bq = (const float*)d_in[4];
    const float* Wk = (const float*)d_in[5];
    const float* bk = (const float*)d_in[6];
    const float* Wv = (const float*)d_in[7];
    const float* bv = (const float*)d_in[8];
    // d_in[9] = mask: reference mask is exactly causal tril; handled analytically.
    float* out = (float*)d_out;

    float *gq, *gk, *gv;
    cudaGetSymbolAddress((void**)&gq, g_q);
    cudaGetSymbolAddress((void**)&gk, g_k);
    cudaGetSymbolAddress((void**)&gv, g_v);

    dim3 pgrid(DDIM / 64, (BNUM * SLEN) / 64);
    proj_kernel<<<pgrid, 128>>>(q, Wq, bq, gq);
    proj_kernel<<<pgrid, 128>>>(k, Wk, bk, gk);
    proj_kernel<<<pgrid, 128>>>(v, Wv, bv, gv);

    const size_t smem_bytes = (size_t)(3*64*65 + 64*68) * sizeof(float); // 67328
    cudaFuncSetAttribute(attn_kernel,
                         cudaFuncAttributeMaxDynamicSharedMemorySize,
                         (int)smem_bytes);
    attn_kernel<<<dim3(BNUM*HNUM, SLEN/64), 128, smem_bytes>>>(gq, gk, gv, out);
}

// round 3
// speedup vs baseline: 1.7811x; 1.7811x over previous
#include <cuda_runtime.h>
#include <cstdint>

#define BNUM 2
#define SLEN 2048
#define DDIM 1024
#define HNUM 16
#define DKQ  64

// Scratch: projected Q/K/V in [B, H, S, DK] layout + transposed weights [N, K].
__device__ float g_q[BNUM*HNUM*SLEN*DKQ];
__device__ float g_k[BNUM*HNUM*SLEN*DKQ];
__device__ float g_v[BNUM*HNUM*SLEN*DKQ];
__device__ float g_wt[3][DDIM*DDIM];

// ---------------- helpers ----------------
__device__ __forceinline__ uint32_t f2tf32(float x) {
    uint32_t y;
    asm("cvt.rna.tf32.f32 %0, %1;" : "=r"(y) : "f"(x));
    return y;
}

__device__ __forceinline__ void mma_tf32(
    float& d0, float& d1, float& d2, float& d3,
    uint32_t a0, uint32_t a1, uint32_t a2, uint32_t a3,
    uint32_t b0, uint32_t b1)
{
    asm volatile(
        "mma.sync.aligned.m16n8k8.row.col.f32.tf32.tf32.f32 "
        "{%0,%1,%2,%3}, {%4,%5,%6,%7}, {%8,%9}, {%0,%1,%2,%3};"
        : "+f"(d0), "+f"(d1), "+f"(d2), "+f"(d3)
        : "r"(a0), "r"(a1), "r"(a2), "r"(a3), "r"(b0), "r"(b1));
}

// ---------------- weight transpose: Wt[n][k] = W[k][n] ----------------
__global__ __launch_bounds__(256) void transpose_kernel(
    const float* __restrict__ in, float* __restrict__ out)
{
    __shared__ float t[32][33];
    int x = blockIdx.x*32 + threadIdx.x;
    int y0 = blockIdx.y*32 + threadIdx.y;
#pragma unroll
    for (int j = 0; j < 32; j += 8)
        t[threadIdx.y + j][threadIdx.x] = in[(size_t)(y0 + j)*DDIM + x];
    __syncthreads();
    int xo = blockIdx.y*32 + threadIdx.x;
    int yo = blockIdx.x*32 + threadIdx.y;
#pragma unroll
    for (int j = 0; j < 32; j += 8)
        out[(size_t)(yo + j)*DDIM + xo] = t[threadIdx.x][threadIdx.y + j];
}

// ---------------- tf32 HMMA projection GEMM ----------------
// C[4096,1024] = A[4096,1024] @ Wt[1024,1024]^T + bias, out in [B,H,S,DK].
// Block tile 128x128, K-chunk 32. 8 warps (2x4), warp tile 64x32 via
// m16n8k8 tf32 mma.sync. Smem rows padded 32->36: both the writer STS.128
// and all fragment LDS.32 are bank-conflict-free (bank = const + lane).
__global__ __launch_bounds__(256, 2) void proj_mma_kernel(
    const float* __restrict__ A, const float* __restrict__ Wt,
    const float* __restrict__ bias, float* __restrict__ out)
{
    __shared__ uint32_t As[128][36];
    __shared__ uint32_t Bs[128][36];

    const int tid  = threadIdx.x;
    const int wid  = tid >> 5;
    const int lane = tid & 31;
    const int lr   = lane >> 2;     // 0..7
    const int lc   = lane & 3;      // 0..3
    const int wm   = (wid >> 2) * 64;   // warp m offset in tile
    const int wn   = (wid & 3) * 32;    // warp n offset in tile
    const int col0 = blockIdx.x << 7;
    const int row0 = blockIdx.y << 7;

    float acc[4][4][4];
#pragma unroll
    for (int mt = 0; mt < 4; mt++)
#pragma unroll
        for (int nt = 0; nt < 4; nt++)
#pragma unroll
            for (int i = 0; i < 4; i++) acc[mt][nt][i] = 0.f;

    for (int kc = 0; kc < DDIM; kc += 32) {
        __syncthreads();
        // Load 128x32 of A and of Wt, convert to tf32, store padded rows.
#pragma unroll
        for (int it = 0; it < 4; it++) {
            int f  = tid + it * 256;       // 0..1023
            int r  = f >> 3;
            int c4 = (f & 7) << 2;
            float4 va = *(const float4*)(A  + (size_t)(row0 + r) * DDIM + kc + c4);
            float4 vb = *(const float4*)(Wt + (size_t)(col0 + r) * DDIM + kc + c4);
            uint4 ua = { f2tf32(va.x), f2tf32(va.y), f2tf32(va.z), f2tf32(va.w) };
            uint4 ub = { f2tf32(vb.x), f2tf32(vb.y), f2tf32(vb.z), f2tf32(vb.w) };
            *(uint4*)&As[r][c4] = ua;
            *(uint4*)&Bs[r][c4] = ub;
        }
        __syncthreads();

#pragma unroll
        for (int ks = 0; ks < 4; ks++) {
            const int k8 = ks * 8;
            uint32_t a[4][4];
#pragma unroll
            for (int mt = 0; mt < 4; mt++) {
                int r = wm + mt * 16 + lr;
                a[mt][0] = As[r    ][k8 + lc];
                a[mt][1] = As[r + 8][k8 + lc];
                a[mt][2] = As[r    ][k8 + lc + 4];
                a[mt][3] = As[r + 8][k8 + lc + 4];
            }
#pragma unroll
            for (int nt = 0; nt < 4; nt++) {
                int n = wn + nt * 8 + lr;
                uint32_t b0 = Bs[n][k8 + lc];
                uint32_t b1 = Bs[n][k8 + lc + 4];
#pragma unroll
                for (int mt = 0; mt < 4; mt++)
                    mma_tf32(acc[mt][nt][0], acc[mt][nt][1],
                             acc[mt][nt][2], acc[mt][nt][3],
                             a[mt][0], a[mt][1], a[mt][2], a[mt][3], b0, b1);
            }
        }
    }

    // Epilogue: write directly to [B,H,S,DK] scratch with fused bias.
#pragma unroll
    for (int mt = 0; mt < 4; mt++) {
#pragma unroll
        for (int nt = 0; nt < 4; nt++) {
            int row = row0 + wm + mt * 16 + lr;
            int col = col0 + wn + nt * 8 + 2 * lc;
            float2 bb = *(const float2*)(bias + col);
            int head = col >> 6;
            int dk   = col & 63;
            int b0i  = row >> 11;
            int s0   = row & (SLEN - 1);
            float2 v0 = { acc[mt][nt][0] + bb.x, acc[mt][nt][1] + bb.y };
            *(float2*)(out + ((size_t)(b0i * HNUM + head) * SLEN + s0) * DKQ + dk) = v0;
            int row2 = row + 8;
            int b1i  = row2 >> 11;
            int s1   = row2 & (SLEN - 1);
            float2 v1 = { acc[mt][nt][2] + bb.x, acc[mt][nt][3] + bb.y };
            *(float2*)(out + ((size_t)(b1i * HNUM + head) * SLEN + s1) * DKQ + dk) = v1;
        }
    }
}

// ---------------- flash attention (unchanged, known-good) ----------------
__global__ __launch_bounds__(128) void attn_kernel(
    const float* __restrict__ Q, const float* __restrict__ K,
    const float* __restrict__ V, float* __restrict__ out)
{
    extern __shared__ float smem[];
    float* Qst = smem;               // 64*65
    float* Kst = smem + 64*65;       // 64*65
    float* Pst = smem + 2*64*65;     // 64*65
    float* Vs  = smem + 3*64*65;     // 64*68

    const int tid = threadIdx.x;
    const int rg  = tid >> 3;
    const int cg  = tid & 7;
    const int bh  = blockIdx.x;
    const int qt  = blockIdx.y;

    const float* Qb = Q + ((size_t)bh * SLEN + (size_t)qt * 64) * DKQ;

#pragma unroll
    for (int it = 0; it < 8; it++) {
        int f = tid + it * 128;
        int r = f >> 4, c = (f & 15) << 2;
        float4 v4 = *(const float4*)(Qb + r * DKQ + c);
        Qst[(c+0)*65 + r] = v4.x;
        Qst[(c+1)*65 + r] = v4.y;
        Qst[(c+2)*65 + r] = v4.z;
        Qst[(c+3)*65 + r] = v4.w;
    }

    float m[4], l[4], acc[4][8];
#pragma unroll
    for (int i = 0; i < 4; i++) {
        m[i] = -1e30f; l[i] = 0.f;
#pragma unroll
        for (int j = 0; j < 8; j++) acc[i][j] = 0.f;
    }

    const float scale = 0.125f;
    const int q0 = qt*64 + rg*4;

    for (int kt = 0; kt <= qt; kt++) {
        __syncthreads();
        const float* Kb = K + ((size_t)bh * SLEN + (size_t)kt * 64) * DKQ;
        const float* Vb = V + ((size_t)bh * SLEN + (size_t)kt * 64) * DKQ;
#pragma unroll
        for (int it = 0; it < 8; it++) {
            int f = tid + it * 128;
            int r = f >> 4, c = (f & 15) << 2;
            float4 k4 = *(const float4*)(Kb + r * DKQ + c);
            Kst[(c+0)*65 + r] = k4.x;
            Kst[(c+1)*65 + r] = k4.y;
            Kst[(c+2)*65 + r] = k4.z;
            Kst[(c+3)*65 + r] = k4.w;
            *(float4*)&Vs[r*68 + c] = *(const float4*)(Vb + r * DKQ + c);
        }
        __syncthreads();

        float sc[4][8];
#pragma unroll
        for (int i = 0; i < 4; i++)
#pragma unroll
            for (int j = 0; j < 8; j++) sc[i][j] = 0.f;

#pragma unroll 8
        for (int d = 0; d < 64; d++) {
            float a[4], b[8];
#pragma unroll
            for (int i = 0; i < 4; i++) a[i] = Qst[d*65 + rg*4 + i];
#pragma unroll
            for (int j = 0; j < 8; j++) b[j] = Kst[d*65 + cg*8 + j];
#pragma unroll
            for (int i = 0; i < 4; i++)
#pragma unroll
                for (int j = 0; j < 8; j++)
                    sc[i][j] = fmaf(a[i], b[j], sc[i][j]);
        }

        const int k0 = kt*64 + cg*8;
        if (kt == qt) {
#pragma unroll
            for (int i = 0; i < 4; i++)
#pragma unroll
                for (int j = 0; j < 8; j++)
                    sc[i][j] = (k0 + j > q0 + i) ? -1e30f : sc[i][j] * scale;
        } else {
#pragma unroll
            for (int i = 0; i < 4; i++)
#pragma unroll
                for (int j = 0; j < 8; j++) sc[i][j] *= scale;
        }

#pragma unroll
        for (int i = 0; i < 4; i++) {
            float rmax = sc[i][0];
#pragma unroll
            for (int j = 1; j < 8; j++) rmax = fmaxf(rmax, sc[i][j]);
#pragma unroll
            for (int off = 1; off < 8; off <<= 1)
                rmax = fmaxf(rmax, __shfl_xor_sync(0xffffffffu, rmax, off));
            float mn   = fmaxf(m[i], rmax);
            float corr = __expf(m[i] - mn);
            float rsum = 0.f;
#pragma unroll
            for (int j = 0; j < 8; j++) {
                sc[i][j] = __expf(sc[i][j] - mn);
                rsum += sc[i][j];
            }
#pragma unroll
            for (int off = 1; off < 8; off <<= 1)
                rsum += __shfl_xor_sync(0xffffffffu, rsum, off);
            l[i] = l[i] * corr + rsum;
            m[i] = mn;
#pragma unroll
            for (int j = 0; j < 8; j++) {
                acc[i][j] *= corr;
                Pst[(cg*8 + j)*65 + rg*4 + i] = sc[i][j];
            }
        }
        __syncthreads();

#pragma unroll 8
        for (int kk = 0; kk < 64; kk++) {
            float a[4], b[8];
#pragma unroll
            for (int i = 0; i < 4; i++) a[i] = Pst[kk*65 + rg*4 + i];
#pragma unroll
            for (int j = 0; j < 8; j++) b[j] = Vs[kk*68 + cg*8 + j];
#pragma unroll
            for (int i = 0; i < 4; i++)
#pragma unroll
                for (int j = 0; j < 8; j++)
                    acc[i][j] = fmaf(a[i], b[j], acc[i][j]);
        }
    }

    const int b = bh >> 4, h = bh & 15;
#pragma unroll
    for (int i = 0; i < 4; i++) {
        int srow = qt*64 + rg*4 + i;
        float inv = 1.f / l[i];
        float* orow = out + ((size_t)b * SLEN + srow) * DDIM + h * DKQ + cg*8;
#pragma unroll
        for (int j = 0; j < 8; j++)
            orow[j] = acc[i][j] * inv;
    }
}

extern "C" void kernel_launch(void* const* d_in, const int* in_sizes, int n_in,
                              void* d_out, int out_size) {
    const float* q  = (const float*)d_in[0];
    const float* k  = (const float*)d_in[1];
    const float* v  = (const float*)d_in[2];
    const float* Wq = (const float*)d_in[3];
    const float* bq = (const float*)d_in[4];
    const float* Wk = (const float*)d_in[5];
    const float* bk = (const float*)d_in[6];
    const float* Wv = (const float*)d_in[7];
    const float* bv = (const float*)d_in[8];
    float* out = (float*)d_out;

    float *gq, *gk, *gv, *gwt;
    cudaGetSymbolAddress((void**)&gq, g_q);
    cudaGetSymbolAddress((void**)&gk, g_k);
    cudaGetSymbolAddress((void**)&gv, g_v);
    cudaGetSymbolAddress((void**)&gwt, g_wt);

    // Transpose the 3 weight matrices to [N, K].
    dim3 tgrid(DDIM/32, DDIM/32), tblk(32, 8);
    transpose_kernel<<<tgrid, tblk>>>(Wq, gwt + 0*DDIM*DDIM);
    transpose_kernel<<<tgrid, tblk>>>(Wk, gwt + 1*DDIM*DDIM);
    transpose_kernel<<<tgrid, tblk>>>(Wv, gwt + 2*DDIM*DDIM);

    // tf32 HMMA projections.
    dim3 pgrid(DDIM/128, (BNUM*SLEN)/128);
    proj_mma_kernel<<<pgrid, 256>>>(q, gwt + 0*DDIM*DDIM, bq, gq);
    proj_mma_kernel<<<pgrid, 256>>>(k, gwt + 1*DDIM*DDIM, bk, gk);
    proj_mma_kernel<<<pgrid, 256>>>(v, gwt + 2*DDIM*DDIM, bv, gv);

    const size_t smem_bytes = (size_t)(3*64*65 + 64*68) * sizeof(float); // 67328
    cudaFuncSetAttribute(attn_kernel,
                         cudaFuncAttributeMaxDynamicSharedMemorySize,
                         (int)smem_bytes);
    attn_kernel<<<dim3(BNUM*HNUM, SLEN/64), 128, smem_bytes>>>(gq, gk, gv, out);
}

// round 4
// speedup vs baseline: 3.2516x; 1.8257x over previous
#include <cuda_runtime.h>
#include <cstdint>

#define BNUM 2
#define SLEN 2048
#define DDIM 1024
#define HNUM 16
#define DKQ  64
#define PAD  68

// Scratch: projected Q/K/V in [B, H, S, DK] layout + transposed weights [N, K].
__device__ float g_q[BNUM*HNUM*SLEN*DKQ];
__device__ float g_k[BNUM*HNUM*SLEN*DKQ];
__device__ float g_v[BNUM*HNUM*SLEN*DKQ];
__device__ float g_wt[3][DDIM*DDIM];

// ---------------- helpers ----------------
__device__ __forceinline__ uint32_t f2tf32(float x) {
    uint32_t y;
    asm("cvt.rna.tf32.f32 %0, %1;" : "=r"(y) : "f"(x));
    return y;
}
__device__ __forceinline__ void split_tf32(float x, uint32_t& hi, uint32_t& lo) {
    hi = f2tf32(x);
    lo = f2tf32(x - __uint_as_float(hi));
}
__device__ __forceinline__ void mma_tf32(
    float& d0, float& d1, float& d2, float& d3,
    uint32_t a0, uint32_t a1, uint32_t a2, uint32_t a3,
    uint32_t b0, uint32_t b1)
{
    asm volatile(
        "mma.sync.aligned.m16n8k8.row.col.f32.tf32.tf32.f32 "
        "{%0,%1,%2,%3}, {%4,%5,%6,%7}, {%8,%9}, {%0,%1,%2,%3};"
        : "+f"(d0), "+f"(d1), "+f"(d2), "+f"(d3)
        : "r"(a0), "r"(a1), "r"(a2), "r"(a3), "r"(b0), "r"(b1));
}

// ---------------- weight transpose: Wt[n][k] = W[k][n] ----------------
__global__ __launch_bounds__(256) void transpose_kernel(
    const float* __restrict__ in, float* __restrict__ out)
{
    __shared__ float t[32][33];
    int x = blockIdx.x*32 + threadIdx.x;
    int y0 = blockIdx.y*32 + threadIdx.y;
#pragma unroll
    for (int j = 0; j < 32; j += 8)
        t[threadIdx.y + j][threadIdx.x] = in[(size_t)(y0 + j)*DDIM + x];
    __syncthreads();
    int xo = blockIdx.y*32 + threadIdx.x;
    int yo = blockIdx.x*32 + threadIdx.y;
#pragma unroll
    for (int j = 0; j < 32; j += 8)
        out[(size_t)(yo + j)*DDIM + xo] = t[threadIdx.x][threadIdx.y + j];
}

// ---------------- tf32 HMMA projection GEMM (unchanged, proven) ----------------
__global__ __launch_bounds__(256, 2) void proj_mma_kernel(
    const float* __restrict__ A, const float* __restrict__ Wt,
    const float* __restrict__ bias, float* __restrict__ out)
{
    __shared__ uint32_t As[128][36];
    __shared__ uint32_t Bs[128][36];

    const int tid  = threadIdx.x;
    const int wid  = tid >> 5;
    const int lane = tid & 31;
    const int lr   = lane >> 2;
    const int lc   = lane & 3;
    const int wm   = (wid >> 2) * 64;
    const int wn   = (wid & 3) * 32;
    const int col0 = blockIdx.x << 7;
    const int row0 = blockIdx.y << 7;

    float acc[4][4][4];
#pragma unroll
    for (int mt = 0; mt < 4; mt++)
#pragma unroll
        for (int nt = 0; nt < 4; nt++)
#pragma unroll
            for (int i = 0; i < 4; i++) acc[mt][nt][i] = 0.f;

    for (int kc = 0; kc < DDIM; kc += 32) {
        __syncthreads();
#pragma unroll
        for (int it = 0; it < 4; it++) {
            int f  = tid + it * 256;
            int r  = f >> 3;
            int c4 = (f & 7) << 2;
            float4 va = *(const float4*)(A  + (size_t)(row0 + r) * DDIM + kc + c4);
            float4 vb = *(const float4*)(Wt + (size_t)(col0 + r) * DDIM + kc + c4);
            uint4 ua = { f2tf32(va.x), f2tf32(va.y), f2tf32(va.z), f2tf32(va.w) };
            uint4 ub = { f2tf32(vb.x), f2tf32(vb.y), f2tf32(vb.z), f2tf32(vb.w) };
            *(uint4*)&As[r][c4] = ua;
            *(uint4*)&Bs[r][c4] = ub;
        }
        __syncthreads();

#pragma unroll
        for (int ks = 0; ks < 4; ks++) {
            const int k8 = ks * 8;
            uint32_t a[4][4];
#pragma unroll
            for (int mt = 0; mt < 4; mt++) {
                int r = wm + mt * 16 + lr;
                a[mt][0] = As[r    ][k8 + lc];
                a[mt][1] = As[r + 8][k8 + lc];
                a[mt][2] = As[r    ][k8 + lc + 4];
                a[mt][3] = As[r + 8][k8 + lc + 4];
            }
#pragma unroll
            for (int nt = 0; nt < 4; nt++) {
                int n = wn + nt * 8 + lr;
                uint32_t b0 = Bs[n][k8 + lc];
                uint32_t b1 = Bs[n][k8 + lc + 4];
#pragma unroll
                for (int mt = 0; mt < 4; mt++)
                    mma_tf32(acc[mt][nt][0], acc[mt][nt][1],
                             acc[mt][nt][2], acc[mt][nt][3],
                             a[mt][0], a[mt][1], a[mt][2], a[mt][3], b0, b1);
            }
        }
    }

#pragma unroll
    for (int mt = 0; mt < 4; mt++) {
#pragma unroll
        for (int nt = 0; nt < 4; nt++) {
            int row = row0 + wm + mt * 16 + lr;
            int col = col0 + wn + nt * 8 + 2 * lc;
            float2 bb = *(const float2*)(bias + col);
            int head = col >> 6;
            int dk   = col & 63;
            int b0i  = row >> 11;
            int s0   = row & (SLEN - 1);
            float2 v0 = { acc[mt][nt][0] + bb.x, acc[mt][nt][1] + bb.y };
            *(float2*)(out + ((size_t)(b0i * HNUM + head) * SLEN + s0) * DKQ + dk) = v0;
            int row2 = row + 8;
            int b1i  = row2 >> 11;
            int s1   = row2 & (SLEN - 1);
            float2 v1 = { acc[mt][nt][2] + bb.x, acc[mt][nt][3] + bb.y };
            *(float2*)(out + ((size_t)(b1i * HNUM + head) * SLEN + s1) * DKQ + dk) = v1;
        }
    }
}

// ---------------- tensor-core flash attention ----------------
// One CTA = (bh, 64-query tile), 128 threads (4 warps), warp = 16 q-rows.
// QK^T: tf32x3 (error-free scores). PV: plain tf32. All hot-path fragment
// LDS are conflict-free with row stride PAD=68 (bank = 4*lr + lc + const).
__global__ __launch_bounds__(128) void attn_mma_kernel(
    const float* __restrict__ Q, const float* __restrict__ K,
    const float* __restrict__ V, float* __restrict__ out)
{
    extern __shared__ uint32_t sm[];
    uint32_t* Qhi = sm;                 // [64][PAD] q-rows x dk
    uint32_t* Qlo = Qhi + 64*PAD;
    uint32_t* Khi = Qlo + 64*PAD;       // [64][PAD] keys x dk
    uint32_t* Klo = Khi + 64*PAD;
    uint32_t* Vt  = Klo + 64*PAD;       // [64][PAD] d x keys (transposed)
    uint32_t* Ps  = Vt  + 64*PAD;       // [64][PAD] q-rows x keys (tf32)

    const int tid  = threadIdx.x;
    const int w    = tid >> 5;
    const int lane = tid & 31;
    const int lr   = lane >> 2;
    const int lc   = lane & 3;
    const int bh   = blockIdx.x;
    const int qt   = (gridDim.y - 1) - blockIdx.y;  // big tiles first

    // Load Q tile, pre-scaled by 1/sqrt(dk)=0.125, split into hi/lo tf32.
    const float* Qb = Q + ((size_t)bh * SLEN + (size_t)qt * 64) * DKQ;
#pragma unroll
    for (int it = 0; it < 8; it++) {
        int f = tid + it * 128;
        int r = f >> 4, c = (f & 15) << 2;
        float4 v4 = *(const float4*)(Qb + r * DKQ + c);
        v4.x *= 0.125f; v4.y *= 0.125f; v4.z *= 0.125f; v4.w *= 0.125f;
        uint4 hi, lo;
        split_tf32(v4.x, hi.x, lo.x); split_tf32(v4.y, hi.y, lo.y);
        split_tf32(v4.z, hi.z, lo.z); split_tf32(v4.w, hi.w, lo.w);
        *(uint4*)&Qhi[r*PAD + c] = hi;
        *(uint4*)&Qlo[r*PAD + c] = lo;
    }

    float accO[8][4];
#pragma unroll
    for (int nf = 0; nf < 8; nf++)
#pragma unroll
        for (int i = 0; i < 4; i++) accO[nf][i] = 0.f;
    float mrow[2] = { -1e30f, -1e30f };
    float lrow[2] = { 0.f, 0.f };

    const int qrow0 = qt*64 + w*16 + lr;   // global query row of half 0 (+8 for half 1)
    const int qbase = (w*16 + lr) * PAD;   // Ps/Q row offset half 0

    for (int kt = 0; kt <= qt; kt++) {
        __syncthreads();   // previous iteration's K/V/P consumers are done
        const float* Kb = K + ((size_t)bh * SLEN + (size_t)kt * 64) * DKQ;
        const float* Vb = V + ((size_t)bh * SLEN + (size_t)kt * 64) * DKQ;
#pragma unroll
        for (int it = 0; it < 8; it++) {
            int f = tid + it * 128;
            int r = f >> 4, c = (f & 15) << 2;
            float4 k4 = *(const float4*)(Kb + r * DKQ + c);
            uint4 hi, lo;
            split_tf32(k4.x, hi.x, lo.x); split_tf32(k4.y, hi.y, lo.y);
            split_tf32(k4.z, hi.z, lo.z); split_tf32(k4.w, hi.w, lo.w);
            *(uint4*)&Khi[r*PAD + c] = hi;
            *(uint4*)&Klo[r*PAD + c] = lo;
            // V: column-wise thread mapping -> conflict-free transposed STS
            int rv = f & 63, cv = (f >> 6) << 2;
            float4 vv = *(const float4*)(Vb + rv * DKQ + cv);
            Vt[(cv+0)*PAD + rv] = f2tf32(vv.x);
            Vt[(cv+1)*PAD + rv] = f2tf32(vv.y);
            Vt[(cv+2)*PAD + rv] = f2tf32(vv.z);
            Vt[(cv+3)*PAD + rv] = f2tf32(vv.w);
        }
        __syncthreads();

        // ---- scores: tf32x3 QK^T ----
        float accS[8][4];
#pragma unroll
        for (int nf = 0; nf < 8; nf++)
#pragma unroll
            for (int i = 0; i < 4; i++) accS[nf][i] = 0.f;

#pragma unroll
        for (int ks = 0; ks < 8; ks++) {
            const int k8 = ks * 8;
            uint32_t ah0 = Qhi[qbase + k8 + lc];
            uint32_t ah2 = Qhi[qbase + k8 + lc + 4];
            uint32_t ah1 = Qhi[qbase + 8*PAD + k8 + lc];
            uint32_t ah3 = Qhi[qbase + 8*PAD + k8 + lc + 4];
            uint32_t al0 = Qlo[qbase + k8 + lc];
            uint32_t al2 = Qlo[qbase + k8 + lc + 4];
            uint32_t al1 = Qlo[qbase + 8*PAD + k8 + lc];
            uint32_t al3 = Qlo[qbase + 8*PAD + k8 + lc + 4];
#pragma unroll
            for (int nf = 0; nf < 8; nf++) {
                int nb = (nf*8 + lr) * PAD + k8 + lc;
                uint32_t bh0 = Khi[nb], bh1 = Khi[nb + 4];
                uint32_t bl0 = Klo[nb], bl1 = Klo[nb + 4];
                mma_tf32(accS[nf][0], accS[nf][1], accS[nf][2], accS[nf][3],
                         ah0, ah1, ah2, ah3, bh0, bh1);
                mma_tf32(accS[nf][0], accS[nf][1], accS[nf][2], accS[nf][3],
                         ah0, ah1, ah2, ah3, bl0, bl1);
                mma_tf32(accS[nf][0], accS[nf][1], accS[nf][2], accS[nf][3],
                         al0, al1, al2, al3, bh0, bh1);
            }
        }

        // ---- causal mask on diagonal tile ----
        if (kt == qt) {
#pragma unroll
            for (int nf = 0; nf < 8; nf++) {
                int gc = kt*64 + nf*8 + 2*lc;
                if (gc     > qrow0)     accS[nf][0] = -1e30f;
                if (gc + 1 > qrow0)     accS[nf][1] = -1e30f;
                if (gc     > qrow0 + 8) accS[nf][2] = -1e30f;
                if (gc + 1 > qrow0 + 8) accS[nf][3] = -1e30f;
            }
        }

        // ---- online softmax (two row-halves per thread) ----
#pragma unroll
        for (int h = 0; h < 2; h++) {
            const int i0 = 2*h, i1 = 2*h + 1;
            float rmax = accS[0][i0];
#pragma unroll
            for (int nf = 0; nf < 8; nf++) {
                rmax = fmaxf(rmax, accS[nf][i0]);
                rmax = fmaxf(rmax, accS[nf][i1]);
            }
            rmax = fmaxf(rmax, __shfl_xor_sync(0xffffffffu, rmax, 1));
            rmax = fmaxf(rmax, __shfl_xor_sync(0xffffffffu, rmax, 2));
            float mn   = fmaxf(mrow[h], rmax);
            float corr = __expf(mrow[h] - mn);
            mrow[h] = mn;
            float rsum = 0.f;
            const int pb = qbase + h*8*PAD;
#pragma unroll
            for (int nf = 0; nf < 8; nf++) {
                uint32_t u0 = f2tf32(__expf(accS[nf][i0] - mn));
                uint32_t u1 = f2tf32(__expf(accS[nf][i1] - mn));
                rsum += __uint_as_float(u0) + __uint_as_float(u1);
                uint2 pp = { u0, u1 };
                *(uint2*)&Ps[pb + nf*8 + 2*lc] = pp;
                accO[nf][i0] *= corr;
                accO[nf][i1] *= corr;
            }
            rsum += __shfl_xor_sync(0xffffffffu, rsum, 1);
            rsum += __shfl_xor_sync(0xffffffffu, rsum, 2);
            lrow[h] = lrow[h] * corr + rsum;
        }
        __syncwarp();   // P rows are produced & consumed by this warp only

        // ---- accO += P @ V (plain tf32) ----
#pragma unroll
        for (int ks = 0; ks < 8; ks++) {
            const int k8 = ks * 8;
            uint32_t a0 = Ps[qbase + k8 + lc];
            uint32_t a2 = Ps[qbase + k8 + lc + 4];
            uint32_t a1 = Ps[qbase + 8*PAD + k8 + lc];
            uint32_t a3 = Ps[qbase + 8*PAD + k8 + lc + 4];
#pragma unroll
            for (int nf = 0; nf < 8; nf++) {
                int nb = (nf*8 + lr) * PAD + k8 + lc;
                uint32_t b0 = Vt[nb], b1 = Vt[nb + 4];
                mma_tf32(accO[nf][0], accO[nf][1], accO[nf][2], accO[nf][3],
                         a0, a1, a2, a3, b0, b1);
            }
        }
    }

    // ---- epilogue: out[B,S,D] ----
    const int b = bh >> 4, h = bh & 15;
    const float inv0 = 1.f / lrow[0];
    const float inv1 = 1.f / lrow[1];
    const int s0 = qt*64 + w*16 + lr;
    const int s1 = s0 + 8;
#pragma unroll
    for (int nf = 0; nf < 8; nf++) {
        int col = h*DKQ + nf*8 + 2*lc;
        float2 v0 = { accO[nf][0] * inv0, accO[nf][1] * inv0 };
        float2 v1 = { accO[nf][2] * inv1, accO[nf][3] * inv1 };
        *(float2*)(out + ((size_t)b * SLEN + s0) * DDIM + col) = v0;
        *(float2*)(out + ((size_t)b * SLEN + s1) * DDIM + col) = v1;
    }
}

extern "C" void kernel_launch(void* const* d_in, const int* in_sizes, int n_in,
                              void* d_out, int out_size) {
    const float* q  = (const float*)d_in[0];
    const float* k  = (const float*)d_in[1];
    const float* v  = (const float*)d_in[2];
    const float* Wq = (const float*)d_in[3];
    const float* bq = (const float*)d_in[4];
    const float* Wk = (const float*)d_in[5];
    const float* bk = (const float*)d_in[6];
    const float* Wv = (const float*)d_in[7];
    const float* bv = (const float*)d_in[8];
    float* out = (float*)d_out;

    float *gq, *gk, *gv, *gwt;
    cudaGetSymbolAddress((void**)&gq, g_q);
    cudaGetSymbolAddress((void**)&gk, g_k);
    cudaGetSymbolAddress((void**)&gv, g_v);
    cudaGetSymbolAddress((void**)&gwt, g_wt);

    dim3 tgrid(DDIM/32, DDIM/32), tblk(32, 8);
    transpose_kernel<<<tgrid, tblk>>>(Wq, gwt + 0*DDIM*DDIM);
    transpose_kernel<<<tgrid, tblk>>>(Wk, gwt + 1*DDIM*DDIM);
    transpose_kernel<<<tgrid, tblk>>>(Wv, gwt + 2*DDIM*DDIM);

    dim3 pgrid(DDIM/128, (BNUM*SLEN)/128);
    proj_mma_kernel<<<pgrid, 256>>>(q, gwt + 0*DDIM*DDIM, bq, gq);
    proj_mma_kernel<<<pgrid, 256>>>(k, gwt + 1*DDIM*DDIM, bk, gk);
    proj_mma_kernel<<<pgrid, 256>>>(v, gwt + 2*DDIM*DDIM, bv, gv);

    const int attn_smem = 6 * 64 * PAD * 4;   // 104448 bytes
    cudaFuncSetAttribute(attn_mma_kernel,
                         cudaFuncAttributeMaxDynamicSharedMemorySize, attn_smem);
    attn_mma_kernel<<<dim3(BNUM*HNUM, SLEN/64), 128, attn_smem>>>(gq, gk, gv, out);
}